// round 15
// baseline (speedup 1.0000x reference)
#include <cuda_runtime.h>
#include <cuda_bf16.h>
#include <math.h>
#include <stdint.h>

#define NNODES 10000
#define NPAD   10112     // 79*128
#define NHID   128
#define NBPAD  1088
#define EMAX   160000

// ---------------- scratch (device globals; no allocation allowed) ----------
__device__ float g_X0[NNODES * NHID];          // final-layer z (decoder input)
__device__ float g_Xf[NNODES * NHID];          // current-layer X fp32 (gather src)
__device__ float g_V [NNODES * 1024];          // [conv(512) | res(512)]
__device__ float g_as[NNODES * 4];
__device__ float g_ad[NNODES * 4];
__device__ float g_fold[8 * 128];              // rows 0..3 src folds, 4..7 dst folds
__device__ __nv_bfloat16 g_Xhi [NPAD * 128];   // X split (res GEMM input)
__device__ __nv_bfloat16 g_Xlo [NPAD * 128];
__device__ __nv_bfloat16 g_AGGhi[4 * NPAD * 128];  // per-head aggregated X (split)
__device__ __nv_bfloat16 g_AGGlo[4 * NPAD * 128];
__device__ __nv_bfloat16 g_XIhi[NPAD * 256];   // encoder input x (split)
__device__ __nv_bfloat16 g_XIlo[NPAD * 256];
__device__ __nv_bfloat16 g_Whi[NBPAD * 128];   // gat_w(0..511) | res_w(512..1023)
__device__ __nv_bfloat16 g_Wlo[NBPAD * 128];
__device__ __nv_bfloat16 g_Ehi[128 * 256];     // enc_w (split)
__device__ __nv_bfloat16 g_Elo[128 * 256];
__device__ int   g_deg[NNODES];
__device__ int   g_cur[NNODES];
__device__ int   g_off[NNODES + 1];
__device__ int   g_csr[EMAX];
__device__ int   g_is64;

// ---------------- helpers ---------------------------------------------------
__device__ __forceinline__ float lrelu(float x) { return x > 0.f ? x : 0.2f * x; }
__device__ __forceinline__ float eluf (float x) { return x > 0.f ? x : (__expf(x) - 1.f); }

__device__ __forceinline__ unsigned long long pk2(float lo, float hi) {
    unsigned long long r;
    asm("mov.b64 %0, {%1, %2};" : "=l"(r) : "f"(lo), "f"(hi));
    return r;
}
__device__ __forceinline__ void fma2(unsigned long long& d,
                                     unsigned long long a, unsigned long long b) {
    asm("fma.rn.f32x2 %0, %1, %2, %3;" : "=l"(d) : "l"(a), "l"(b), "l"(d));
}
__device__ __forceinline__ void upk2(float& lo, float& hi, unsigned long long v) {
    asm("mov.b64 {%0, %1}, %2;" : "=f"(lo), "=f"(hi) : "l"(v));
}

__device__ __forceinline__ int edge_at(const void* ei, int idx, int is64) {
    if (is64) return (int)((const long long*)ei)[idx];
    return ((const int*)ei)[idx];
}

__device__ __forceinline__ uint32_t smem_u32(const void* p) {
    uint32_t a;
    asm("{ .reg .u64 t; cvta.to.shared.u64 t, %1; cvt.u32.u64 %0, t; }"
        : "=r"(a) : "l"(p));
    return a;
}

#define LDSM_X4(r, addr)                                                        \
    asm volatile("ldmatrix.sync.aligned.m8n8.x4.shared.b16 {%0,%1,%2,%3}, [%4];" \
        : "=r"((r)[0]), "=r"((r)[1]), "=r"((r)[2]), "=r"((r)[3]) : "r"(addr))

#define MMA_BF16(c, a, b0_, b1_)                                                \
    asm volatile("mma.sync.aligned.m16n8k16.row.col.f32.bf16.bf16.f32 "         \
        "{%0,%1,%2,%3}, {%4,%5,%6,%7}, {%8,%9}, {%0,%1,%2,%3};"                 \
        : "+f"((c)[0]), "+f"((c)[1]), "+f"((c)[2]), "+f"((c)[3])                \
        : "r"((a)[0]), "r"((a)[1]), "r"((a)[2]), "r"((a)[3]), "r"(b0_), "r"(b1_))

__device__ __forceinline__ void split_write(__nv_bfloat16* hi, __nv_bfloat16* lo,
                                            size_t idx, float v) {
    __nv_bfloat16 h = __float2bfloat16(v);
    hi[idx] = h;
    lo[idx] = __float2bfloat16(v - __bfloat162float(h));
}

// ---------------- init: fold rows (blocks 0..7) + dtype sniff (block 8) -----
__global__ __launch_bounds__(128)
void init_kernel(const void* ei,
                 const float* __restrict__ gat_w,
                 const float* __restrict__ att_src,
                 const float* __restrict__ att_dst)
{
    int b = blockIdx.x, t = threadIdx.x;
    if (b < 8) {
        int h = b & 3;
        const float* att = (b < 4) ? att_src : att_dst;
        float s = 0.f;
        for (int k = 0; k < 128; k++)
            s = fmaf(att[h * 128 + k], gat_w[(size_t)(h * 128 + k) * 128 + t], s);
        g_fold[b * 128 + t] = s;
    } else {
        __shared__ int acc[128];
        const unsigned* w = (const unsigned*)ei;
        unsigned o = 0;
        #pragma unroll
        for (int j = 0; j < 16; j++) o |= w[(t + j * 128) * 2 + 1];
        acc[t] = (int)(o != 0);
        __syncthreads();
        for (int s = 64; s > 0; s >>= 1) {
            if (t < s) acc[t] |= acc[t + s];
            __syncthreads();
        }
        if (t == 0) g_is64 = acc[0] ? 0 : 1;
    }
}

// ---------------- weight conversions -----------------------------------------
__global__ __launch_bounds__(128)
void conv_w_kernel(const float* __restrict__ gat_w,
                   const float* __restrict__ res_w)
{
    int r = blockIdx.x, t = threadIdx.x;   // 1024 blocks
    float v = (r < 512) ? gat_w[(size_t)r * 128 + t]
                        : res_w[(size_t)(r - 512) * 128 + t];
    split_write(g_Whi, g_Wlo, (size_t)r * 128 + t, v);
}

__global__ __launch_bounds__(256)
void conv_ew_kernel(const float* __restrict__ enc_w)
{
    int r = blockIdx.x, t = threadIdx.x;
    split_write(g_Ehi, g_Elo, (size_t)r * 256 + t, enc_w[(size_t)r * 256 + t]);
}

__global__ __launch_bounds__(256)
void conv_xin_kernel(const float* __restrict__ x)
{
    int idx = blockIdx.x * 256 + threadIdx.x;
    float v = (idx < NNODES * 256) ? x[idx] : 0.f;
    split_write(g_XIhi, g_XIlo, idx, v);
}

// ---------------- CSR build -------------------------------------------------
__global__ void count_kernel(const void* __restrict__ ei, int E) {
    int e = blockIdx.x * blockDim.x + threadIdx.x;
    if (e < E) atomicAdd(&g_deg[edge_at(ei, E + e, g_is64)], 1);
}

__global__ void scan_kernel(int n) {
    __shared__ int wsum[32];
    int t = threadIdx.x, lane = t & 31, w = t >> 5;
    const int chunk = 10;
    int base_i = t * chunk;
    int s = 0;
    #pragma unroll
    for (int i = 0; i < chunk; i++) {
        int idx = base_i + i;
        if (idx < n) s += g_deg[idx];
    }
    int v = s;
    #pragma unroll
    for (int o = 1; o < 32; o <<= 1) {
        int u = __shfl_up_sync(0xffffffffu, v, o);
        if (lane >= o) v += u;
    }
    if (lane == 31) wsum[w] = v;
    __syncthreads();
    if (w == 0) {
        int xv = wsum[lane];
        #pragma unroll
        for (int o = 1; o < 32; o <<= 1) {
            int u = __shfl_up_sync(0xffffffffu, xv, o);
            if (lane >= o) xv += u;
        }
        wsum[lane] = xv;
    }
    __syncthreads();
    int run = (w ? wsum[w - 1] : 0) + v - s;
    #pragma unroll
    for (int i = 0; i < chunk; i++) {
        int idx = base_i + i;
        if (idx < n) { g_off[idx] = run; run += g_deg[idx]; }
    }
    if (t == 1023) g_off[n] = run;
}

__global__ void scatter_kernel(const void* __restrict__ ei, int E) {
    int e = blockIdx.x * blockDim.x + threadIdx.x;
    if (e < E) {
        int is64 = g_is64;
        int d = edge_at(ei, E + e, is64);
        int p = g_off[d] + atomicAdd(&g_cur[d], 1);
        g_csr[p] = edge_at(ei, e, is64);
    }
}

// ---------------- SIMT GEMM (decoder) ----------------------------------------
__global__ __launch_bounds__(256)
void gemm_dec(const float* __restrict__ B,
              const float* __restrict__ bias,
              float* __restrict__ C,
              int M, int N, int K)
{
    const float* A = g_X0;
    __shared__ float As[2][16][132];
    __shared__ float Bs[2][16][68];

    const int tid = threadIdx.x;
    const int tx = tid & 15, ty = tid >> 4;
    const int am0 = tid >> 2, am1 = 64 + (tid >> 2), ak4 = tid & 3;
    const int bn0 = tid >> 2, bk4 = tid & 3;
    const int bm = blockIdx.x * 128;

    const float* brow = B + (size_t)bn0 * K;

    float4 pa0, pa1, pb;
    const int nt = K >> 4;

    {
        int gm0 = bm + am0, gm1 = bm + am1;
        pa0 = (gm0 < M) ? *(const float4*)(A + (size_t)gm0 * K + ak4 * 4) : make_float4(0, 0, 0, 0);
        pa1 = (gm1 < M) ? *(const float4*)(A + (size_t)gm1 * K + ak4 * 4) : make_float4(0, 0, 0, 0);
        pb  = (bn0 < N) ? *(const float4*)(brow + bk4 * 4) : make_float4(0, 0, 0, 0);
        As[0][ak4 * 4 + 0][am0] = pa0.x; As[0][ak4 * 4 + 1][am0] = pa0.y;
        As[0][ak4 * 4 + 2][am0] = pa0.z; As[0][ak4 * 4 + 3][am0] = pa0.w;
        As[0][ak4 * 4 + 0][am1] = pa1.x; As[0][ak4 * 4 + 1][am1] = pa1.y;
        As[0][ak4 * 4 + 2][am1] = pa1.z; As[0][ak4 * 4 + 3][am1] = pa1.w;
        Bs[0][bk4 * 4 + 0][bn0] = pb.x;  Bs[0][bk4 * 4 + 1][bn0] = pb.y;
        Bs[0][bk4 * 4 + 2][bn0] = pb.z;  Bs[0][bk4 * 4 + 3][bn0] = pb.w;
    }
    __syncthreads();

    unsigned long long acc[4][4];
    const unsigned long long zz = pk2(0.f, 0.f);
    #pragma unroll
    for (int i = 0; i < 4; i++)
        #pragma unroll
        for (int j = 0; j < 4; j++) acc[i][j] = zz;

    for (int t = 0; t < nt; t++) {
        int cur = t & 1;
        if (t + 1 < nt) {
            int kt = (t + 1) << 4;
            int gm0 = bm + am0, gm1 = bm + am1;
            pa0 = (gm0 < M) ? *(const float4*)(A + (size_t)gm0 * K + kt + ak4 * 4) : make_float4(0, 0, 0, 0);
            pa1 = (gm1 < M) ? *(const float4*)(A + (size_t)gm1 * K + kt + ak4 * 4) : make_float4(0, 0, 0, 0);
            pb  = (bn0 < N) ? *(const float4*)(brow + kt + bk4 * 4) : make_float4(0, 0, 0, 0);
        }
        #pragma unroll
        for (int k = 0; k < 16; k++) {
            ulonglong2 ap0 = *(const ulonglong2*)&As[cur][k][ty * 8];
            ulonglong2 ap1 = *(const ulonglong2*)&As[cur][k][ty * 8 + 4];
            float4 bv = *(const float4*)&Bs[cur][k][tx * 4];
            unsigned long long ad[4] = {ap0.x, ap0.y, ap1.x, ap1.y};
            unsigned long long bd[4] = {pk2(bv.x, bv.x), pk2(bv.y, bv.y),
                                        pk2(bv.z, bv.z), pk2(bv.w, bv.w)};
            #pragma unroll
            for (int i = 0; i < 4; i++) {
                fma2(acc[i][0], ad[i], bd[0]);
                fma2(acc[i][1], ad[i], bd[1]);
                fma2(acc[i][2], ad[i], bd[2]);
                fma2(acc[i][3], ad[i], bd[3]);
            }
        }
        if (t + 1 < nt) {
            int nxt = cur ^ 1;
            As[nxt][ak4 * 4 + 0][am0] = pa0.x; As[nxt][ak4 * 4 + 1][am0] = pa0.y;
            As[nxt][ak4 * 4 + 2][am0] = pa0.z; As[nxt][ak4 * 4 + 3][am0] = pa0.w;
            As[nxt][ak4 * 4 + 0][am1] = pa1.x; As[nxt][ak4 * 4 + 1][am1] = pa1.y;
            As[nxt][ak4 * 4 + 2][am1] = pa1.z; As[nxt][ak4 * 4 + 3][am1] = pa1.w;
            Bs[nxt][bk4 * 4 + 0][bn0] = pb.x;  Bs[nxt][bk4 * 4 + 1][bn0] = pb.y;
            Bs[nxt][bk4 * 4 + 2][bn0] = pb.z;  Bs[nxt][bk4 * 4 + 3][bn0] = pb.w;
            __syncthreads();
        }
    }

    #pragma unroll
    for (int i2 = 0; i2 < 4; i2++) {
        #pragma unroll
        for (int p = 0; p < 2; p++) {
            int gm = bm + ty * 8 + i2 * 2 + p;
            if (gm >= M) continue;
            #pragma unroll
            for (int j = 0; j < 4; j++) {
                float lo, hi;
                upk2(lo, hi, acc[i2][j]);
                float v = p ? hi : lo;
                int gn = tx * 4 + j;
                if (gn >= N) continue;
                v += bias[gn];
                C[(size_t)gm * N + gn] = v;
            }
        }
    }
}

// ---------------- HMMA GEMM (bf16-split-3) -----------------------------------
// EPI 0 (layer): tiles y<8: conv head h=y>>1 (A=AGG_h, B=gat_w rows y*64);
//                tiles 8..15: res (A=X split, B=res_w rows, +res_b). out g_V.
// EPI 1 (encoder): A=XI split (K=256), B=enc_w; out relu -> g_Xf + X split.
template<int EPI>
__global__ __launch_bounds__(256)
void hmma_gemm(const float* __restrict__ bias)
{
    __shared__ __nv_bfloat16 sAh[128][40];
    __shared__ __nv_bfloat16 sAl[128][40];
    __shared__ __nv_bfloat16 sBh[64][40];
    __shared__ __nv_bfloat16 sBl[64][40];

    const int tid = threadIdx.x;
    const int lane = tid & 31, wid = tid >> 5;
    const int wm = wid >> 1, wn = wid & 1;
    const int bm = blockIdx.x * 128;
    const int tn = blockIdx.y;

    const int K = (EPI == 1) ? 256 : 128;
    const __nv_bfloat16 *Ahi, *Alo, *Bhi, *Blo;
    if (EPI == 1) {
        Ahi = g_XIhi; Alo = g_XIlo; Bhi = g_Ehi; Blo = g_Elo;
    } else if (tn < 8) {
        size_t hb = (size_t)(tn >> 1) * NPAD * 128;
        Ahi = g_AGGhi + hb; Alo = g_AGGlo + hb;
        Bhi = g_Whi; Blo = g_Wlo;
    } else {
        Ahi = g_Xhi; Alo = g_Xlo;
        Bhi = g_Whi; Blo = g_Wlo;
    }
    const size_t bnrow = (size_t)tn * 64;

    float acc[2][4][4];
    #pragma unroll
    for (int i = 0; i < 2; i++)
        #pragma unroll
        for (int j = 0; j < 4; j++)
            #pragma unroll
            for (int q = 0; q < 4; q++) acc[i][j][q] = 0.f;

    const uint32_t aHiB = smem_u32(&sAh[0][0]);
    const uint32_t aLoB = smem_u32(&sAl[0][0]);
    const uint32_t bHiB = smem_u32(&sBh[0][0]);
    const uint32_t bLoB = smem_u32(&sBl[0][0]);

    const int aRow = wm * 32 + (lane & 15);
    const int aColOff = (lane >> 4) * 8;
    const int bRow = wn * 32 + (lane & 7) + ((lane >> 4) & 1) * 8;
    const int bColOff = ((lane >> 3) & 1) * 8;

    for (int kc = 0; kc < K; kc += 32) {
        #pragma unroll
        for (int i = 0; i < 2; i++) {
            int idx = tid + i * 256;
            int r = idx >> 2, q = idx & 3;
            size_t src = (size_t)(bm + r) * K + kc + q * 8;
            *(uint4*)&sAh[r][q * 8] = *(const uint4*)(Ahi + src);
            *(uint4*)&sAl[r][q * 8] = *(const uint4*)(Alo + src);
        }
        {
            int r = tid >> 2, q = tid & 3;
            size_t src = (bnrow + r) * K + kc + q * 8;
            *(uint4*)&sBh[r][q * 8] = *(const uint4*)(Bhi + src);
            *(uint4*)&sBl[r][q * 8] = *(const uint4*)(Blo + src);
        }
        __syncthreads();

        #pragma unroll
        for (int ks = 0; ks < 2; ks++) {
            int kk = ks * 16;
            uint32_t ah[2][4], al[2][4];
            #pragma unroll
            for (int mi = 0; mi < 2; mi++) {
                uint32_t off = (uint32_t)(((aRow + mi * 16) * 40 + kk + aColOff) * 2);
                LDSM_X4(ah[mi], aHiB + off);
                LDSM_X4(al[mi], aLoB + off);
            }
            uint32_t bh0[4], bl0[4], bh1[4], bl1[4];
            {
                uint32_t off0 = (uint32_t)((bRow * 40 + kk + bColOff) * 2);
                uint32_t off1 = (uint32_t)(((bRow + 16) * 40 + kk + bColOff) * 2);
                LDSM_X4(bh0, bHiB + off0);
                LDSM_X4(bl0, bLoB + off0);
                LDSM_X4(bh1, bHiB + off1);
                LDSM_X4(bl1, bLoB + off1);
            }
            #pragma unroll
            for (int mi = 0; mi < 2; mi++) {
                MMA_BF16(acc[mi][0], ah[mi], bh0[0], bh0[1]);
                MMA_BF16(acc[mi][0], ah[mi], bl0[0], bl0[1]);
                MMA_BF16(acc[mi][0], al[mi], bh0[0], bh0[1]);
                MMA_BF16(acc[mi][1], ah[mi], bh0[2], bh0[3]);
                MMA_BF16(acc[mi][1], ah[mi], bl0[2], bl0[3]);
                MMA_BF16(acc[mi][1], al[mi], bh0[2], bh0[3]);
                MMA_BF16(acc[mi][2], ah[mi], bh1[0], bh1[1]);
                MMA_BF16(acc[mi][2], ah[mi], bl1[0], bl1[1]);
                MMA_BF16(acc[mi][2], al[mi], bh1[0], bh1[1]);
                MMA_BF16(acc[mi][3], ah[mi], bh1[2], bh1[3]);
                MMA_BF16(acc[mi][3], ah[mi], bl1[2], bl1[3]);
                MMA_BF16(acc[mi][3], al[mi], bh1[2], bh1[3]);
            }
        }
        __syncthreads();
    }

    const int g = lane >> 2, tig = lane & 3;
    #pragma unroll
    for (int mi = 0; mi < 2; mi++) {
        #pragma unroll
        for (int ni = 0; ni < 4; ni++) {
            int gn = tn * 64 + wn * 32 + ni * 8 + tig * 2;
            int gm0 = bm + wm * 32 + mi * 16 + g;
            if (EPI == 0) {
                const bool isres = (tn >= 8);
                float bx = 0.f, by = 0.f;
                if (isres) { bx = bias[gn - 512]; by = bias[gn - 511]; }
                if (gm0 < NNODES) {
                    float2 o = make_float2(acc[mi][ni][0] + bx, acc[mi][ni][1] + by);
                    *(float2*)(g_V + (size_t)gm0 * 1024 + gn) = o;
                }
                int gm1 = gm0 + 8;
                if (gm1 < NNODES) {
                    float2 o = make_float2(acc[mi][ni][2] + bx, acc[mi][ni][3] + by);
                    *(float2*)(g_V + (size_t)gm1 * 1024 + gn) = o;
                }
            } else {
                float bx = bias[gn], by = bias[gn + 1];
                if (gm0 < NNODES) {
                    float vx = fmaxf(acc[mi][ni][0] + bx, 0.f);
                    float vy = fmaxf(acc[mi][ni][1] + by, 0.f);
                    size_t o = (size_t)gm0 * 128 + gn;
                    *(float2*)(g_Xf + o) = make_float2(vx, vy);
                    split_write(g_Xhi, g_Xlo, o, vx);
                    split_write(g_Xhi, g_Xlo, o + 1, vy);
                }
                int gm1 = gm0 + 8;
                if (gm1 < NNODES) {
                    float vx = fmaxf(acc[mi][ni][2] + bx, 0.f);
                    float vy = fmaxf(acc[mi][ni][3] + by, 0.f);
                    size_t o = (size_t)gm1 * 128 + gn;
                    *(float2*)(g_Xf + o) = make_float2(vx, vy);
                    split_write(g_Xhi, g_Xlo, o, vx);
                    split_write(g_Xhi, g_Xlo, o + 1, vy);
                }
            }
        }
    }
}

// ---------------- logits of encoder X (layer 0 only) ------------------------
__global__ __launch_bounds__(128)
void logit_kernel()
{
    int d = blockIdx.x;
    int lane = threadIdx.x & 31, w = threadIdx.x >> 5;
    const float* xr = g_Xf + (size_t)d * 128;
    float p0 = 0.f, p1 = 0.f;
    #pragma unroll
    for (int i = 0; i < 4; i++) {
        float v = xr[lane + i * 32];
        p0 = fmaf(g_fold[w * 128 + lane + i * 32], v, p0);
        p1 = fmaf(g_fold[(w + 4) * 128 + lane + i * 32], v, p1);
    }
    #pragma unroll
    for (int o = 16; o > 0; o >>= 1) {
        p0 += __shfl_down_sync(0xffffffffu, p0, o);
        p1 += __shfl_down_sync(0xffffffffu, p1, o);
    }
    if (lane == 0) { g_as[d * 4 + w] = p0; g_ad[d * 4 + w] = p1; }
}

// ---------------- node aggregation over X (512B per edge) -------------------
// one block per dst node, 128 threads (thread = channel c). Softmax stabilized
// by the self logit; per-edge weights computed once into smem.
// AGG_h[d, c] = (X[d,c] + sum_e w_h(e) X[src,c]) / (1 + sum_e w_h(e))
template<int ZERO>
__global__ __launch_bounds__(128)
void node_agg_kernel()
{
    const int d = blockIdx.x, t = threadIdx.x;

    __shared__ float s_adv[4];
    __shared__ float s_ls [4];
    __shared__ float sw[128];
    __shared__ int   si[32];

    if (t < 4) {
        float adv = g_ad[d * 4 + t];
        s_adv[t] = adv;
        s_ls[t]  = lrelu(g_as[d * 4 + t] + adv);
    }
    if (ZERO && t == 0) { g_deg[d] = 0; g_cur[d] = 0; }
    __syncthreads();

    const int e0 = g_off[d], e1 = g_off[d + 1];

    float xd = g_Xf[(size_t)d * 128 + t];
    float a0 = xd, a1 = xd, a2 = xd, a3 = xd;
    float s0 = 1.f, s1 = 1.f, s2 = 1.f, s3 = 1.f;

    const int jj = t >> 2, hh = t & 3;
    const float adv_h = s_adv[hh];
    const float ls_h  = s_ls[hh];

    for (int base = e0; base < e1; base += 32) {
        int cnt = min(32, e1 - base);
        if (jj < cnt) {
            int s = g_csr[base + jj];
            if (hh == 0) si[jj] = s;
            float as = g_as[s * 4 + hh];
            sw[jj * 4 + hh] = __expf(lrelu(as + adv_h) - ls_h);
        }
        __syncthreads();

        int j = 0;
        for (; j + 2 <= cnt; j += 2) {
            float4 w0 = *(const float4*)&sw[j * 4];
            float4 w1 = *(const float4*)&sw[j * 4 + 4];
            float x0 = g_Xf[(size_t)si[j] * 128 + t];
            float x1 = g_Xf[(size_t)si[j + 1] * 128 + t];
            a0 = fmaf(w0.x, x0, a0); s0 += w0.x;
            a1 = fmaf(w0.y, x0, a1); s1 += w0.y;
            a2 = fmaf(w0.z, x0, a2); s2 += w0.z;
            a3 = fmaf(w0.w, x0, a3); s3 += w0.w;
            a0 = fmaf(w1.x, x1, a0); s0 += w1.x;
            a1 = fmaf(w1.y, x1, a1); s1 += w1.y;
            a2 = fmaf(w1.z, x1, a2); s2 += w1.z;
            a3 = fmaf(w1.w, x1, a3); s3 += w1.w;
        }
        if (j < cnt) {
            float4 w0 = *(const float4*)&sw[j * 4];
            float x0 = g_Xf[(size_t)si[j] * 128 + t];
            a0 = fmaf(w0.x, x0, a0); s0 += w0.x;
            a1 = fmaf(w0.y, x0, a1); s1 += w0.y;
            a2 = fmaf(w0.z, x0, a2); s2 += w0.z;
            a3 = fmaf(w0.w, x0, a3); s3 += w0.w;
        }
        __syncthreads();
    }

    size_t o = (size_t)d * 128 + t;
    split_write(g_AGGhi,                  g_AGGlo,                  o, a0 * (1.f / s0));
    split_write(g_AGGhi + (size_t)NPAD * 128,     g_AGGlo + (size_t)NPAD * 128,     o, a1 * (1.f / s1));
    split_write(g_AGGhi + (size_t)NPAD * 256,     g_AGGlo + (size_t)NPAD * 256,     o, a2 * (1.f / s2));
    split_write(g_AGGhi + (size_t)NPAD * 384,     g_AGGlo + (size_t)NPAD * 384,     o, a3 * (1.f / s3));
}

// ---------------- epilogue: z = mean_h elu(conv + gat_b + res) --------------
// MODE 0: writes Xf fp32 + splits + next-layer logits
// MODE 1: writes g_X0 (decoder input) only
template<int MODE>
__global__ __launch_bounds__(128)
void epi_kernel(const float* __restrict__ gat_b)
{
    __shared__ float sz[128];
    const int d = blockIdx.x, t = threadIdx.x;
    const float* vd = g_V + (size_t)d * 1024;
    float4 cv = ((const float4*)vd)[t];
    float4 rs = ((const float4*)(vd + 512))[t];
    float4 gb = ((const float4*)gat_b)[t];
    float z = 0.25f * (eluf(cv.x + rs.x + gb.x) +
                       eluf(cv.y + rs.y + gb.y) +
                       eluf(cv.z + rs.z + gb.z) +
                       eluf(cv.w + rs.w + gb.w));
    size_t o = (size_t)d * 128 + t;
    if (MODE == 1) {
        g_X0[o] = z;
        return;
    }
    sz[t] = z;
    g_Xf[o] = z;
    split_write(g_Xhi, g_Xlo, o, z);
    __syncthreads();
    int lane = t & 31, w = t >> 5;
    float p0 = 0.f, p1 = 0.f;
    #pragma unroll
    for (int i = 0; i < 4; i++) {
        float v = sz[lane + i * 32];
        p0 = fmaf(g_fold[w * 128 + lane + i * 32], v, p0);
        p1 = fmaf(g_fold[(w + 4) * 128 + lane + i * 32], v, p1);
    }
    #pragma unroll
    for (int ofs = 16; ofs > 0; ofs >>= 1) {
        p0 += __shfl_down_sync(0xffffffffu, p0, ofs);
        p1 += __shfl_down_sync(0xffffffffu, p1, ofs);
    }
    if (lane == 0) { g_as[d * 4 + w] = p0; g_ad[d * 4 + w] = p1; }
}

// ---------------- host ------------------------------------------------------
extern "C" void kernel_launch(void* const* d_in, const int* in_sizes, int n_in,
                              void* d_out, int out_size)
{
    const float* x       = (const float*)d_in[0];
    const void*  ei      = d_in[1];
    const float* enc_w   = (const float*)d_in[2];
    const float* enc_b   = (const float*)d_in[3];
    const float* res_w   = (const float*)d_in[4];
    const float* res_b   = (const float*)d_in[5];
    const float* gat_w   = (const float*)d_in[6];
    const float* att_src = (const float*)d_in[7];
    const float* att_dst = (const float*)d_in[8];
    const float* gat_b   = (const float*)d_in[9];
    const float* dec_w   = (const float*)d_in[10];
    const float* dec_b   = (const float*)d_in[11];
    int E = in_sizes[1] / 2;

    cudaStream_t s2;
    cudaStreamCreateWithFlags(&s2, cudaStreamNonBlocking);
    cudaEvent_t evA, evB;
    cudaEventCreateWithFlags(&evA, cudaEventDisableTiming);
    cudaEventCreateWithFlags(&evB, cudaEventDisableTiming);

    // folds + dtype sniff (small, fast)
    init_kernel<<<9, 128>>>(ei, gat_w, att_src, att_dst);

    // fork EARLY: CSR build on side stream, overlapping conv + encoder
    cudaEventRecord(evA, 0);
    cudaStreamWaitEvent(s2, evA, 0);
    count_kernel<<<(E + 255) / 256, 256, 0, s2>>>(ei, E);
    scan_kernel<<<1, 1024, 0, s2>>>(NNODES);
    scatter_kernel<<<(E + 255) / 256, 256, 0, s2>>>(ei, E);
    cudaEventRecord(evB, s2);

    // conversions on main stream (overlap with CSR)
    conv_w_kernel<<<1024, 128>>>(gat_w, res_w);
    conv_ew_kernel<<<128, 256>>>(enc_w);
    conv_xin_kernel<<<NPAD * 256 / 256, 256>>>(x);

    // encoder (HMMA): Xf = relu(x @ enc_w^T + enc_b) (+splits)
    hmma_gemm<1><<<dim3(79, 2), 256>>>(enc_b);
    logit_kernel<<<NNODES, 128>>>();

    // layer 0
    cudaStreamWaitEvent(0, evB, 0);
    node_agg_kernel<1><<<NNODES, 128>>>();
    hmma_gemm<0><<<dim3(79, 16), 256>>>(res_b);
    epi_kernel<0><<<NNODES, 128>>>(gat_b);

    // layer 1
    node_agg_kernel<0><<<NNODES, 128>>>();
    hmma_gemm<0><<<dim3(79, 16), 256>>>(res_b);
    epi_kernel<1><<<NNODES, 128>>>(gat_b);

    // decoder: out = z @ dec_w^T + dec_b
    gemm_dec<<<79, 256>>>(dec_w, dec_b, (float*)d_out, NNODES, 40, 128);
}

// round 16
// speedup vs baseline: 1.2941x; 1.2941x over previous
#include <cuda_runtime.h>
#include <cuda_bf16.h>
#include <math.h>
#include <stdint.h>

#define NNODES 10000
#define NPAD   10112     // 79*128
#define NHID   128
#define UC     1032      // U row: xh(512) | res(512) | a_src(4) | a_dst(4)
#define NBPAD  1088      // 17*64
#define EMAX   160000

// ---------------- scratch (device globals; no allocation allowed) ----------
__device__ float g_X0[NNODES * NHID];          // final-layer z (decoder input)
__device__ float g_U [NNODES * UC];
__device__ float g_fold[8 * 128];
__device__ __nv_bfloat16 g_Xhi [NPAD * 128];   // current-layer activations (split)
__device__ __nv_bfloat16 g_Xlo [NPAD * 128];
__device__ __nv_bfloat16 g_XIhi[NPAD * 256];   // encoder input x (split)
__device__ __nv_bfloat16 g_XIlo[NPAD * 256];
__device__ __nv_bfloat16 g_Whi[NBPAD * 128];   // layer weights (split; rows>=1032 stay 0)
__device__ __nv_bfloat16 g_Wlo[NBPAD * 128];
__device__ __nv_bfloat16 g_Ehi[128 * 256];     // enc_w (split)
__device__ __nv_bfloat16 g_Elo[128 * 256];
__device__ int   g_deg[NNODES];
__device__ int   g_cur[NNODES];
__device__ int   g_off[NNODES + 1];
__device__ int   g_csr[EMAX];
__device__ int   g_is64;

// ---------------- helpers ---------------------------------------------------
__device__ __forceinline__ float lrelu(float x) { return x > 0.f ? x : 0.2f * x; }
__device__ __forceinline__ float eluf (float x) { return x > 0.f ? x : (__expf(x) - 1.f); }

__device__ __forceinline__ unsigned long long pk2(float lo, float hi) {
    unsigned long long r;
    asm("mov.b64 %0, {%1, %2};" : "=l"(r) : "f"(lo), "f"(hi));
    return r;
}
__device__ __forceinline__ void fma2(unsigned long long& d,
                                     unsigned long long a, unsigned long long b) {
    asm("fma.rn.f32x2 %0, %1, %2, %3;" : "=l"(d) : "l"(a), "l"(b), "l"(d));
}
__device__ __forceinline__ void upk2(float& lo, float& hi, unsigned long long v) {
    asm("mov.b64 {%0, %1}, %2;" : "=f"(lo), "=f"(hi) : "l"(v));
}

__device__ __forceinline__ int edge_at(const void* ei, int idx, int is64) {
    if (is64) return (int)((const long long*)ei)[idx];
    return ((const int*)ei)[idx];
}

__device__ __forceinline__ uint32_t smem_u32(const void* p) {
    uint32_t a;
    asm("{ .reg .u64 t; cvta.to.shared.u64 t, %1; cvt.u32.u64 %0, t; }"
        : "=r"(a) : "l"(p));
    return a;
}

#define LDSM_X4(r, addr)                                                        \
    asm volatile("ldmatrix.sync.aligned.m8n8.x4.shared.b16 {%0,%1,%2,%3}, [%4];" \
        : "=r"((r)[0]), "=r"((r)[1]), "=r"((r)[2]), "=r"((r)[3]) : "r"(addr))

#define MMA_BF16(c, a, b0_, b1_)                                                \
    asm volatile("mma.sync.aligned.m16n8k16.row.col.f32.bf16.bf16.f32 "         \
        "{%0,%1,%2,%3}, {%4,%5,%6,%7}, {%8,%9}, {%0,%1,%2,%3};"                 \
        : "+f"((c)[0]), "+f"((c)[1]), "+f"((c)[2]), "+f"((c)[3])                \
        : "r"((a)[0]), "r"((a)[1]), "r"((a)[2]), "r"((a)[3]), "r"(b0_), "r"(b1_))

__device__ __forceinline__ void split_write(__nv_bfloat16* hi, __nv_bfloat16* lo,
                                            size_t idx, float v) {
    __nv_bfloat16 h = __float2bfloat16(v);
    hi[idx] = h;
    lo[idx] = __float2bfloat16(v - __bfloat162float(h));
}

// packed: write (idx, idx+1) as one bf16x2 store each for hi and lo (idx even)
__device__ __forceinline__ void split_write2(__nv_bfloat16* hi, __nv_bfloat16* lo,
                                             size_t idx, float vx, float vy) {
    __nv_bfloat16 hx = __float2bfloat16(vx);
    __nv_bfloat16 hy = __float2bfloat16(vy);
    __nv_bfloat162 hp; hp.x = hx; hp.y = hy;
    *(__nv_bfloat162*)(hi + idx) = hp;
    __nv_bfloat162 lp;
    lp.x = __float2bfloat16(vx - __bfloat162float(hx));
    lp.y = __float2bfloat16(vy - __bfloat162float(hy));
    *(__nv_bfloat162*)(lo + idx) = lp;
}

// ---------------- init: fold rows (blocks 0..7) + dtype sniff (block 8) -----
__global__ __launch_bounds__(128)
void init_kernel(const void* ei,
                 const float* __restrict__ gat_w,
                 const float* __restrict__ att_src,
                 const float* __restrict__ att_dst)
{
    int b = blockIdx.x, t = threadIdx.x;
    if (b < 8) {
        int h = b & 3;
        const float* att = (b < 4) ? att_src : att_dst;
        float s = 0.f;
        for (int k = 0; k < 128; k++)
            s = fmaf(att[h * 128 + k], gat_w[(size_t)(h * 128 + k) * 128 + t], s);
        g_fold[b * 128 + t] = s;
    } else {
        __shared__ int acc[128];
        const unsigned* w = (const unsigned*)ei;
        unsigned o = 0;
        #pragma unroll
        for (int j = 0; j < 16; j++) o |= w[(t + j * 128) * 2 + 1];
        acc[t] = (int)(o != 0);
        __syncthreads();
        for (int s = 64; s > 0; s >>= 1) {
            if (t < s) acc[t] |= acc[t + s];
            __syncthreads();
        }
        if (t == 0) g_is64 = acc[0] ? 0 : 1;
    }
}

// ---------------- weight conversions -----------------------------------------
__global__ __launch_bounds__(128)
void conv_w_kernel(const float* __restrict__ gat_w,
                   const float* __restrict__ res_w)
{
    int r = blockIdx.x, t = threadIdx.x;
    float v = 0.f;
    if (r < 512)       v = gat_w[(size_t)r * 128 + t];
    else if (r < 1024) v = res_w[(size_t)(r - 512) * 128 + t];
    else if (r < 1032) v = g_fold[(r - 1024) * 128 + t];
    split_write(g_Whi, g_Wlo, (size_t)r * 128 + t, v);
}

__global__ __launch_bounds__(256)
void conv_ew_kernel(const float* __restrict__ enc_w)
{
    int r = blockIdx.x, t = threadIdx.x;          // 128 blocks x 256 threads
    split_write(g_Ehi, g_Elo, (size_t)r * 256 + t, enc_w[(size_t)r * 256 + t]);
}

__global__ __launch_bounds__(256)
void conv_xin_kernel(const float* __restrict__ x)
{
    int idx = blockIdx.x * 256 + threadIdx.x;     // < NPAD*256
    float v = (idx < NNODES * 256) ? x[idx] : 0.f;
    split_write(g_XIhi, g_XIlo, idx, v);
}

// ---------------- CSR build -------------------------------------------------
__global__ void count_kernel(const void* __restrict__ ei, int E) {
    int e = blockIdx.x * blockDim.x + threadIdx.x;
    if (e < E) atomicAdd(&g_deg[edge_at(ei, E + e, g_is64)], 1);
}

__global__ void scan_kernel(int n) {
    __shared__ int wsum[32];
    int t = threadIdx.x, lane = t & 31, w = t >> 5;
    const int chunk = 10;
    int base_i = t * chunk;
    int s = 0;
    #pragma unroll
    for (int i = 0; i < chunk; i++) {
        int idx = base_i + i;
        if (idx < n) s += g_deg[idx];
    }
    int v = s;
    #pragma unroll
    for (int o = 1; o < 32; o <<= 1) {
        int u = __shfl_up_sync(0xffffffffu, v, o);
        if (lane >= o) v += u;
    }
    if (lane == 31) wsum[w] = v;
    __syncthreads();
    if (w == 0) {
        int xv = wsum[lane];
        #pragma unroll
        for (int o = 1; o < 32; o <<= 1) {
            int u = __shfl_up_sync(0xffffffffu, xv, o);
            if (lane >= o) xv += u;
        }
        wsum[lane] = xv;
    }
    __syncthreads();
    int run = (w ? wsum[w - 1] : 0) + v - s;
    #pragma unroll
    for (int i = 0; i < chunk; i++) {
        int idx = base_i + i;
        if (idx < n) { g_off[idx] = run; run += g_deg[idx]; }
    }
    if (t == 1023) g_off[n] = run;
}

__global__ void scatter_kernel(const void* __restrict__ ei, int E) {
    int e = blockIdx.x * blockDim.x + threadIdx.x;
    if (e < E) {
        int is64 = g_is64;
        int d = edge_at(ei, E + e, is64);
        int p = g_off[d] + atomicAdd(&g_cur[d], 1);
        g_csr[p] = edge_at(ei, e, is64);
    }
}

// ---------------- SIMT GEMM (decoder) ----------------------------------------
__global__ __launch_bounds__(256)
void gemm_dec(const float* __restrict__ B,
              const float* __restrict__ bias,
              float* __restrict__ C,
              int M, int N, int K)
{
    const float* A = g_X0;
    __shared__ float As[2][16][132];
    __shared__ float Bs[2][16][68];

    const int tid = threadIdx.x;
    const int tx = tid & 15, ty = tid >> 4;
    const int am0 = tid >> 2, am1 = 64 + (tid >> 2), ak4 = tid & 3;
    const int bn0 = tid >> 2, bk4 = tid & 3;
    const int bm = blockIdx.x * 128, bn = 0;

    const int gn_row = bn + bn0;
    const float* brow = B + (size_t)gn_row * K;

    float4 pa0, pa1, pb;
    const int nt = K >> 4;

    {
        int gm0 = bm + am0, gm1 = bm + am1;
        pa0 = (gm0 < M) ? *(const float4*)(A + (size_t)gm0 * K + ak4 * 4) : make_float4(0, 0, 0, 0);
        pa1 = (gm1 < M) ? *(const float4*)(A + (size_t)gm1 * K + ak4 * 4) : make_float4(0, 0, 0, 0);
        pb  = (gn_row < N) ? *(const float4*)(brow + bk4 * 4) : make_float4(0, 0, 0, 0);
        As[0][ak4 * 4 + 0][am0] = pa0.x; As[0][ak4 * 4 + 1][am0] = pa0.y;
        As[0][ak4 * 4 + 2][am0] = pa0.z; As[0][ak4 * 4 + 3][am0] = pa0.w;
        As[0][ak4 * 4 + 0][am1] = pa1.x; As[0][ak4 * 4 + 1][am1] = pa1.y;
        As[0][ak4 * 4 + 2][am1] = pa1.z; As[0][ak4 * 4 + 3][am1] = pa1.w;
        Bs[0][bk4 * 4 + 0][bn0] = pb.x;  Bs[0][bk4 * 4 + 1][bn0] = pb.y;
        Bs[0][bk4 * 4 + 2][bn0] = pb.z;  Bs[0][bk4 * 4 + 3][bn0] = pb.w;
    }
    __syncthreads();

    unsigned long long acc[4][4];
    const unsigned long long zz = pk2(0.f, 0.f);
    #pragma unroll
    for (int i = 0; i < 4; i++)
        #pragma unroll
        for (int j = 0; j < 4; j++) acc[i][j] = zz;

    for (int t = 0; t < nt; t++) {
        int cur = t & 1;
        if (t + 1 < nt) {
            int kt = (t + 1) << 4;
            int gm0 = bm + am0, gm1 = bm + am1;
            pa0 = (gm0 < M) ? *(const float4*)(A + (size_t)gm0 * K + kt + ak4 * 4) : make_float4(0, 0, 0, 0);
            pa1 = (gm1 < M) ? *(const float4*)(A + (size_t)gm1 * K + kt + ak4 * 4) : make_float4(0, 0, 0, 0);
            pb  = (gn_row < N) ? *(const float4*)(brow + kt + bk4 * 4) : make_float4(0, 0, 0, 0);
        }
        #pragma unroll
        for (int k = 0; k < 16; k++) {
            ulonglong2 ap0 = *(const ulonglong2*)&As[cur][k][ty * 8];
            ulonglong2 ap1 = *(const ulonglong2*)&As[cur][k][ty * 8 + 4];
            float4 bv = *(const float4*)&Bs[cur][k][tx * 4];
            unsigned long long ad[4] = {ap0.x, ap0.y, ap1.x, ap1.y};
            unsigned long long bd[4] = {pk2(bv.x, bv.x), pk2(bv.y, bv.y),
                                        pk2(bv.z, bv.z), pk2(bv.w, bv.w)};
            #pragma unroll
            for (int i = 0; i < 4; i++) {
                fma2(acc[i][0], ad[i], bd[0]);
                fma2(acc[i][1], ad[i], bd[1]);
                fma2(acc[i][2], ad[i], bd[2]);
                fma2(acc[i][3], ad[i], bd[3]);
            }
        }
        if (t + 1 < nt) {
            int nxt = cur ^ 1;
            As[nxt][ak4 * 4 + 0][am0] = pa0.x; As[nxt][ak4 * 4 + 1][am0] = pa0.y;
            As[nxt][ak4 * 4 + 2][am0] = pa0.z; As[nxt][ak4 * 4 + 3][am0] = pa0.w;
            As[nxt][ak4 * 4 + 0][am1] = pa1.x; As[nxt][ak4 * 4 + 1][am1] = pa1.y;
            As[nxt][ak4 * 4 + 2][am1] = pa1.z; As[nxt][ak4 * 4 + 3][am1] = pa1.w;
            Bs[nxt][bk4 * 4 + 0][bn0] = pb.x;  Bs[nxt][bk4 * 4 + 1][bn0] = pb.y;
            Bs[nxt][bk4 * 4 + 2][bn0] = pb.z;  Bs[nxt][bk4 * 4 + 3][bn0] = pb.w;
            __syncthreads();
        }
    }

    #pragma unroll
    for (int i2 = 0; i2 < 4; i2++) {
        #pragma unroll
        for (int p = 0; p < 2; p++) {
            int gm = bm + ty * 8 + i2 * 2 + p;
            if (gm >= M) continue;
            #pragma unroll
            for (int j = 0; j < 4; j++) {
                float lo, hi;
                upk2(lo, hi, acc[i2][j]);
                float v = p ? hi : lo;
                int gn = bn + tx * 4 + j;
                if (gn >= N) continue;
                v += bias[gn];
                C[(size_t)gm * N + gn] = v;
            }
        }
    }
}

// ---------------- HMMA GEMM (bf16-split-3) -----------------------------------
// EPI 0: layer  — A=g_Xhi/g_Xlo (K=128), B=g_Whi/g_Wlo, out g_U (+res_b cols)
// EPI 1: encoder— A=g_XIhi/g_XIlo (K=256), B=g_Ehi/g_Elo, out relu -> split X
template<int EPI>
__global__ __launch_bounds__(256)
void hmma_gemm(const float* __restrict__ bias)
{
    __shared__ __nv_bfloat16 sAh[128][40];
    __shared__ __nv_bfloat16 sAl[128][40];
    __shared__ __nv_bfloat16 sBh[64][40];
    __shared__ __nv_bfloat16 sBl[64][40];

    const int tid = threadIdx.x;
    const int lane = tid & 31, wid = tid >> 5;
    const int wm = wid >> 1, wn = wid & 1;
    const int bm = blockIdx.x * 128;
    const int tn = blockIdx.y;

    const int K   = (EPI == 1) ? 256 : 128;
    const __nv_bfloat16* Ahi = (EPI == 1) ? g_XIhi : g_Xhi;
    const __nv_bfloat16* Alo = (EPI == 1) ? g_XIlo : g_Xlo;
    const __nv_bfloat16* Bhi = (EPI == 1) ? g_Ehi : g_Whi;
    const __nv_bfloat16* Blo = (EPI == 1) ? g_Elo : g_Wlo;
    const size_t bnrow = (size_t)tn * 64;

    float acc[2][4][4];
    #pragma unroll
    for (int i = 0; i < 2; i++)
        #pragma unroll
        for (int j = 0; j < 4; j++)
            #pragma unroll
            for (int q = 0; q < 4; q++) acc[i][j][q] = 0.f;

    const uint32_t aHiB = smem_u32(&sAh[0][0]);
    const uint32_t aLoB = smem_u32(&sAl[0][0]);
    const uint32_t bHiB = smem_u32(&sBh[0][0]);
    const uint32_t bLoB = smem_u32(&sBl[0][0]);

    const int aRow = wm * 32 + (lane & 15);
    const int aColOff = (lane >> 4) * 8;
    const int bRow = wn * 32 + (lane & 7) + ((lane >> 4) & 1) * 8;
    const int bColOff = ((lane >> 3) & 1) * 8;

    for (int kc = 0; kc < K; kc += 32) {
        #pragma unroll
        for (int i = 0; i < 2; i++) {
            int idx = tid + i * 256;
            int r = idx >> 2, q = idx & 3;
            size_t src = (size_t)(bm + r) * K + kc + q * 8;
            *(uint4*)&sAh[r][q * 8] = *(const uint4*)(Ahi + src);
            *(uint4*)&sAl[r][q * 8] = *(const uint4*)(Alo + src);
        }
        {
            int r = tid >> 2, q = tid & 3;
            size_t src = (bnrow + r) * K + kc + q * 8;
            *(uint4*)&sBh[r][q * 8] = *(const uint4*)(Bhi + src);
            *(uint4*)&sBl[r][q * 8] = *(const uint4*)(Blo + src);
        }
        __syncthreads();

        #pragma unroll
        for (int ks = 0; ks < 2; ks++) {
            int kk = ks * 16;
            uint32_t ah[2][4], al[2][4];
            #pragma unroll
            for (int mi = 0; mi < 2; mi++) {
                uint32_t off = (uint32_t)(((aRow + mi * 16) * 40 + kk + aColOff) * 2);
                LDSM_X4(ah[mi], aHiB + off);
                LDSM_X4(al[mi], aLoB + off);
            }
            uint32_t bh0[4], bl0[4], bh1[4], bl1[4];
            {
                uint32_t off0 = (uint32_t)((bRow * 40 + kk + bColOff) * 2);
                uint32_t off1 = (uint32_t)(((bRow + 16) * 40 + kk + bColOff) * 2);
                LDSM_X4(bh0, bHiB + off0);
                LDSM_X4(bl0, bLoB + off0);
                LDSM_X4(bh1, bHiB + off1);
                LDSM_X4(bl1, bLoB + off1);
            }
            #pragma unroll
            for (int mi = 0; mi < 2; mi++) {
                MMA_BF16(acc[mi][0], ah[mi], bh0[0], bh0[1]);
                MMA_BF16(acc[mi][0], ah[mi], bl0[0], bl0[1]);
                MMA_BF16(acc[mi][0], al[mi], bh0[0], bh0[1]);
                MMA_BF16(acc[mi][1], ah[mi], bh0[2], bh0[3]);
                MMA_BF16(acc[mi][1], ah[mi], bl0[2], bl0[3]);
                MMA_BF16(acc[mi][1], al[mi], bh0[2], bh0[3]);
                MMA_BF16(acc[mi][2], ah[mi], bh1[0], bh1[1]);
                MMA_BF16(acc[mi][2], ah[mi], bl1[0], bl1[1]);
                MMA_BF16(acc[mi][2], al[mi], bh1[0], bh1[1]);
                MMA_BF16(acc[mi][3], ah[mi], bh1[2], bh1[3]);
                MMA_BF16(acc[mi][3], ah[mi], bl1[2], bl1[3]);
                MMA_BF16(acc[mi][3], al[mi], bh1[2], bh1[3]);
            }
        }
        __syncthreads();
    }

    const int g = lane >> 2, tig = lane & 3;
    #pragma unroll
    for (int mi = 0; mi < 2; mi++) {
        #pragma unroll
        for (int ni = 0; ni < 4; ni++) {
            int gn = tn * 64 + wn * 32 + ni * 8 + tig * 2;
            int gm0 = bm + wm * 32 + mi * 16 + g;
            if (EPI == 0) {
                if (gn >= UC) continue;
                const bool isres = (tn >= 8 && tn < 16);
                float bx = 0.f, by = 0.f;
                if (isres) { bx = bias[gn - 512]; by = bias[gn - 511]; }
                if (gm0 < NNODES) {
                    float2 o = make_float2(acc[mi][ni][0] + bx, acc[mi][ni][1] + by);
                    *(float2*)(g_U + (size_t)gm0 * UC + gn) = o;
                }
                int gm1 = gm0 + 8;
                if (gm1 < NNODES) {
                    float2 o = make_float2(acc[mi][ni][2] + bx, acc[mi][ni][3] + by);
                    *(float2*)(g_U + (size_t)gm1 * UC + gn) = o;
                }
            } else {
                float bx = bias[gn], by = bias[gn + 1];
                if (gm0 < NNODES) {
                    float vx = fmaxf(acc[mi][ni][0] + bx, 0.f);
                    float vy = fmaxf(acc[mi][ni][1] + by, 0.f);
                    split_write2(g_Xhi, g_Xlo, (size_t)gm0 * 128 + gn, vx, vy);
                }
                int gm1 = gm0 + 8;
                if (gm1 < NNODES) {
                    float vx = fmaxf(acc[mi][ni][2] + bx, 0.f);
                    float vy = fmaxf(acc[mi][ni][3] + by, 0.f);
                    split_write2(g_Xhi, g_Xlo, (size_t)gm1 * 128 + gn, vx, vy);
                }
            }
        }
    }
}

// ---------------- GAT aggregation + fused GraphCON epilogue ----------------
// MODE 0: layer 0 — writes split X only (next HMMA input), re-zeroes deg/cur
// MODE 1: layer 1 — writes fp32 g_X0 (decoder input)
template<int MODE>
__global__ __launch_bounds__(128)
void node_kernel(const float* __restrict__ gat_b)
{
    const int d = blockIdx.x, t = threadIdx.x;
    const int h = t >> 5;

    __shared__ float s_adv[4];
    __shared__ float s_ls [4];
    __shared__ float sw[128];
    __shared__ int   si[32];

    const float* ud = g_U + (size_t)d * UC;
    if (t < 4) {
        float adv = ud[1028 + t];
        s_adv[t] = adv;
        s_ls[t]  = lrelu(ud[1024 + t] + adv);
    }
    if (MODE == 0 && t == 0) { g_deg[d] = 0; g_cur[d] = 0; }
    __syncthreads();

    const int e0 = g_off[d], e1 = g_off[d + 1];

    float ssum = 1.f;
    float4 acc = ((const float4*)ud)[t];

    const int jj = t >> 2, hh = t & 3;
    const float adv_h = s_adv[hh];
    const float ls_h  = s_ls[hh];

    for (int base = e0; base < e1; base += 32) {
        int cnt = min(32, e1 - base);
        if (jj < cnt) {
            int s = g_csr[base + jj];
            if (hh == 0) si[jj] = s;
            float as = g_U[(size_t)s * UC + 1024 + hh];
            sw[jj * 4 + hh] = __expf(lrelu(as + adv_h) - ls_h);
        }
        __syncthreads();

        int j = 0;
        for (; j + 4 <= cnt; j += 4) {
            int s0 = si[j], s1 = si[j + 1], s2 = si[j + 2], s3 = si[j + 3];
            float w0 = sw[j * 4 + h],      w1 = sw[j * 4 + 4 + h];
            float w2 = sw[j * 4 + 8 + h],  w3 = sw[j * 4 + 12 + h];
            float4 v0 = ((const float4*)(g_U + (size_t)s0 * UC))[t];
            float4 v1 = ((const float4*)(g_U + (size_t)s1 * UC))[t];
            float4 v2 = ((const float4*)(g_U + (size_t)s2 * UC))[t];
            float4 v3 = ((const float4*)(g_U + (size_t)s3 * UC))[t];
            acc.x = fmaf(w0, v0.x, acc.x); acc.y = fmaf(w0, v0.y, acc.y);
            acc.z = fmaf(w0, v0.z, acc.z); acc.w = fmaf(w0, v0.w, acc.w);
            acc.x = fmaf(w1, v1.x, acc.x); acc.y = fmaf(w1, v1.y, acc.y);
            acc.z = fmaf(w1, v1.z, acc.z); acc.w = fmaf(w1, v1.w, acc.w);
            acc.x = fmaf(w2, v2.x, acc.x); acc.y = fmaf(w2, v2.y, acc.y);
            acc.z = fmaf(w2, v2.z, acc.z); acc.w = fmaf(w2, v2.w, acc.w);
            acc.x = fmaf(w3, v3.x, acc.x); acc.y = fmaf(w3, v3.y, acc.y);
            acc.z = fmaf(w3, v3.z, acc.z); acc.w = fmaf(w3, v3.w, acc.w);
            ssum += (w0 + w1) + (w2 + w3);
        }
        for (; j < cnt; j++) {
            int s0 = si[j];
            float w0 = sw[j * 4 + h];
            float4 v0 = ((const float4*)(g_U + (size_t)s0 * UC))[t];
            acc.x = fmaf(w0, v0.x, acc.x); acc.y = fmaf(w0, v0.y, acc.y);
            acc.z = fmaf(w0, v0.z, acc.z); acc.w = fmaf(w0, v0.w, acc.w);
            ssum += w0;
        }
        __syncthreads();
    }

    float rcp = 1.f / ssum;
    float4 gb = ((const float4*)gat_b)[t];
    float4 rs = ((const float4*)(ud + 512))[t];
    float z = 0.25f * (eluf(fmaf(acc.x, rcp, gb.x + rs.x)) +
                       eluf(fmaf(acc.y, rcp, gb.y + rs.y)) +
                       eluf(fmaf(acc.z, rcp, gb.z + rs.z)) +
                       eluf(fmaf(acc.w, rcp, gb.w + rs.w)));

    size_t o = (size_t)d * NHID + t;
    if (MODE == 0) {
        split_write(g_Xhi, g_Xlo, o, z);
    } else {
        g_X0[o] = z;
    }
}

// ---------------- host ------------------------------------------------------
extern "C" void kernel_launch(void* const* d_in, const int* in_sizes, int n_in,
                              void* d_out, int out_size)
{
    const float* x       = (const float*)d_in[0];
    const void*  ei      = d_in[1];
    const float* enc_w   = (const float*)d_in[2];
    const float* enc_b   = (const float*)d_in[3];
    const float* res_w   = (const float*)d_in[4];
    const float* res_b   = (const float*)d_in[5];
    const float* gat_w   = (const float*)d_in[6];
    const float* att_src = (const float*)d_in[7];
    const float* att_dst = (const float*)d_in[8];
    const float* gat_b   = (const float*)d_in[9];
    const float* dec_w   = (const float*)d_in[10];
    const float* dec_b   = (const float*)d_in[11];
    int E = in_sizes[1] / 2;

    cudaStream_t s2;
    cudaStreamCreateWithFlags(&s2, cudaStreamNonBlocking);
    cudaEvent_t evA, evW, evB;
    cudaEventCreateWithFlags(&evA, cudaEventDisableTiming);
    cudaEventCreateWithFlags(&evW, cudaEventDisableTiming);
    cudaEventCreateWithFlags(&evB, cudaEventDisableTiming);

    // folds + dtype sniff (small, fast)
    init_kernel<<<9, 128>>>(ei, gat_w, att_src, att_dst);

    // fork EARLY: conv_w (needs folds) + CSR build on side stream
    cudaEventRecord(evA, 0);
    cudaStreamWaitEvent(s2, evA, 0);
    conv_w_kernel<<<NBPAD, 128, 0, s2>>>(gat_w, res_w);
    cudaEventRecord(evW, s2);
    count_kernel<<<(E + 255) / 256, 256, 0, s2>>>(ei, E);
    scan_kernel<<<1, 1024, 0, s2>>>(NNODES);
    scatter_kernel<<<(E + 255) / 256, 256, 0, s2>>>(ei, E);
    cudaEventRecord(evB, s2);

    // conversions on main stream (overlap with side-stream work)
    conv_xin_kernel<<<NPAD * 256 / 256, 256>>>(x);
    conv_ew_kernel<<<128, 256>>>(enc_w);

    // encoder (HMMA): split(relu(x @ enc_w^T + enc_b))
    hmma_gemm<1><<<dim3(79, 2), 256>>>(enc_b);

    // layer 0 (GEMM needs conv_w; node needs CSR)
    cudaStreamWaitEvent(0, evW, 0);
    hmma_gemm<0><<<dim3(79, 17), 256>>>(res_b);
    cudaStreamWaitEvent(0, evB, 0);
    node_kernel<0><<<NNODES, 128>>>(gat_b);

    // layer 1
    hmma_gemm<0><<<dim3(79, 17), 256>>>(res_b);
    node_kernel<1><<<NNODES, 128>>>(gat_b);

    // decoder: out = z @ dec_w^T + dec_b
    gemm_dec<<<79, 256>>>(dec_w, dec_b, (float*)d_out, NNODES, 40, 128);
}

// round 17
// speedup vs baseline: 1.3177x; 1.0182x over previous
#include <cuda_runtime.h>
#include <cuda_bf16.h>
#include <math.h>
#include <stdint.h>

#define NNODES 10000
#define NPAD   10112     // 79*128
#define NHID   128
#define UC     1032      // U row: xh(512) | res(512) | a_src(4) | a_dst(4)
#define NBPAD  1088      // 17*64
#define EMAX   160000

// ---------------- scratch (device globals; no allocation allowed) ----------
__device__ float g_X0[NNODES * NHID];          // final-layer z (decoder input)
__device__ float g_U [NNODES * UC];
__device__ float g_fold[8 * 128];
__device__ __nv_bfloat16 g_Xhi [NPAD * 128];   // current-layer activations (split)
__device__ __nv_bfloat16 g_Xlo [NPAD * 128];
__device__ __nv_bfloat16 g_XIhi[NPAD * 256];   // encoder input x (split)
__device__ __nv_bfloat16 g_XIlo[NPAD * 256];
__device__ __nv_bfloat16 g_Whi[NBPAD * 128];   // layer weights (split; rows>=1032 stay 0)
__device__ __nv_bfloat16 g_Wlo[NBPAD * 128];
__device__ __nv_bfloat16 g_Ehi[128 * 256];     // enc_w (split)
__device__ __nv_bfloat16 g_Elo[128 * 256];
__device__ int   g_deg[NNODES];
__device__ int   g_cur[NNODES];
__device__ int   g_off[NNODES + 1];
__device__ int   g_csr[EMAX];
__device__ int   g_is64;

// ---------------- helpers ---------------------------------------------------
__device__ __forceinline__ float lrelu(float x) { return x > 0.f ? x : 0.2f * x; }
__device__ __forceinline__ float eluf (float x) { return x > 0.f ? x : (__expf(x) - 1.f); }

__device__ __forceinline__ unsigned long long pk2(float lo, float hi) {
    unsigned long long r;
    asm("mov.b64 %0, {%1, %2};" : "=l"(r) : "f"(lo), "f"(hi));
    return r;
}
__device__ __forceinline__ void fma2(unsigned long long& d,
                                     unsigned long long a, unsigned long long b) {
    asm("fma.rn.f32x2 %0, %1, %2, %3;" : "=l"(d) : "l"(a), "l"(b), "l"(d));
}
__device__ __forceinline__ void upk2(float& lo, float& hi, unsigned long long v) {
    asm("mov.b64 {%0, %1}, %2;" : "=f"(lo), "=f"(hi) : "l"(v));
}

__device__ __forceinline__ int edge_at(const void* ei, int idx, int is64) {
    if (is64) return (int)((const long long*)ei)[idx];
    return ((const int*)ei)[idx];
}

__device__ __forceinline__ uint32_t smem_u32(const void* p) {
    uint32_t a;
    asm("{ .reg .u64 t; cvta.to.shared.u64 t, %1; cvt.u32.u64 %0, t; }"
        : "=r"(a) : "l"(p));
    return a;
}

#define LDSM_X4(r, addr)                                                        \
    asm volatile("ldmatrix.sync.aligned.m8n8.x4.shared.b16 {%0,%1,%2,%3}, [%4];" \
        : "=r"((r)[0]), "=r"((r)[1]), "=r"((r)[2]), "=r"((r)[3]) : "r"(addr))

#define MMA_BF16(c, a, b0_, b1_)                                                \
    asm volatile("mma.sync.aligned.m16n8k16.row.col.f32.bf16.bf16.f32 "         \
        "{%0,%1,%2,%3}, {%4,%5,%6,%7}, {%8,%9}, {%0,%1,%2,%3};"                 \
        : "+f"((c)[0]), "+f"((c)[1]), "+f"((c)[2]), "+f"((c)[3])                \
        : "r"((a)[0]), "r"((a)[1]), "r"((a)[2]), "r"((a)[3]), "r"(b0_), "r"(b1_))

__device__ __forceinline__ void split_write(__nv_bfloat16* hi, __nv_bfloat16* lo,
                                            size_t idx, float v) {
    __nv_bfloat16 h = __float2bfloat16(v);
    hi[idx] = h;
    lo[idx] = __float2bfloat16(v - __bfloat162float(h));
}

// packed: write (idx, idx+1) as one bf16x2 store each for hi and lo (idx even)
__device__ __forceinline__ void split_write2(__nv_bfloat16* hi, __nv_bfloat16* lo,
                                             size_t idx, float vx, float vy) {
    __nv_bfloat16 hx = __float2bfloat16(vx);
    __nv_bfloat16 hy = __float2bfloat16(vy);
    __nv_bfloat162 hp; hp.x = hx; hp.y = hy;
    *(__nv_bfloat162*)(hi + idx) = hp;
    __nv_bfloat162 lp;
    lp.x = __float2bfloat16(vx - __bfloat162float(hx));
    lp.y = __float2bfloat16(vy - __bfloat162float(hy));
    *(__nv_bfloat162*)(lo + idx) = lp;
}

// ---------------- init: fold rows (blocks 0..7) + dtype sniff (block 8) -----
__global__ __launch_bounds__(128)
void init_kernel(const void* ei,
                 const float* __restrict__ gat_w,
                 const float* __restrict__ att_src,
                 const float* __restrict__ att_dst)
{
    int b = blockIdx.x, t = threadIdx.x;
    if (b < 8) {
        int h = b & 3;
        const float* att = (b < 4) ? att_src : att_dst;
        float s = 0.f;
        for (int k = 0; k < 128; k++)
            s = fmaf(att[h * 128 + k], gat_w[(size_t)(h * 128 + k) * 128 + t], s);
        g_fold[b * 128 + t] = s;
    } else {
        __shared__ int acc[128];
        const unsigned* w = (const unsigned*)ei;
        unsigned o = 0;
        #pragma unroll
        for (int j = 0; j < 16; j++) o |= w[(t + j * 128) * 2 + 1];
        acc[t] = (int)(o != 0);
        __syncthreads();
        for (int s = 64; s > 0; s >>= 1) {
            if (t < s) acc[t] |= acc[t + s];
            __syncthreads();
        }
        if (t == 0) g_is64 = acc[0] ? 0 : 1;
    }
}

// ---------------- weight conversions -----------------------------------------
__global__ __launch_bounds__(128)
void conv_w_kernel(const float* __restrict__ gat_w,
                   const float* __restrict__ res_w)
{
    int r = blockIdx.x, t = threadIdx.x;
    float v = 0.f;
    if (r < 512)       v = gat_w[(size_t)r * 128 + t];
    else if (r < 1024) v = res_w[(size_t)(r - 512) * 128 + t];
    else if (r < 1032) v = g_fold[(r - 1024) * 128 + t];
    split_write(g_Whi, g_Wlo, (size_t)r * 128 + t, v);
}

// xin split (blocks 0..NPAD-1) + enc_w split (blocks NPAD..NPAD+127)
__global__ __launch_bounds__(256)
void conv_x_kernel(const float* __restrict__ x,
                   const float* __restrict__ enc_w)
{
    int b = blockIdx.x, t = threadIdx.x;
    if (b < NPAD) {
        int idx = b * 256 + t;
        float v = (idx < NNODES * 256) ? x[idx] : 0.f;
        split_write(g_XIhi, g_XIlo, idx, v);
    } else {
        int r = b - NPAD;
        split_write(g_Ehi, g_Elo, (size_t)r * 256 + t, enc_w[(size_t)r * 256 + t]);
    }
}

// ---------------- CSR build -------------------------------------------------
__global__ void count_kernel(const void* __restrict__ ei, int E) {
    int e = blockIdx.x * blockDim.x + threadIdx.x;
    if (e < E) atomicAdd(&g_deg[edge_at(ei, E + e, g_is64)], 1);
}

__global__ void scan_kernel(int n) {
    __shared__ int wsum[32];
    int t = threadIdx.x, lane = t & 31, w = t >> 5;
    const int chunk = 10;
    int base_i = t * chunk;
    int s = 0;
    #pragma unroll
    for (int i = 0; i < chunk; i++) {
        int idx = base_i + i;
        if (idx < n) s += g_deg[idx];
    }
    int v = s;
    #pragma unroll
    for (int o = 1; o < 32; o <<= 1) {
        int u = __shfl_up_sync(0xffffffffu, v, o);
        if (lane >= o) v += u;
    }
    if (lane == 31) wsum[w] = v;
    __syncthreads();
    if (w == 0) {
        int xv = wsum[lane];
        #pragma unroll
        for (int o = 1; o < 32; o <<= 1) {
            int u = __shfl_up_sync(0xffffffffu, xv, o);
            if (lane >= o) xv += u;
        }
        wsum[lane] = xv;
    }
    __syncthreads();
    int run = (w ? wsum[w - 1] : 0) + v - s;
    #pragma unroll
    for (int i = 0; i < chunk; i++) {
        int idx = base_i + i;
        if (idx < n) { g_off[idx] = run; run += g_deg[idx]; }
    }
    if (t == 1023) g_off[n] = run;
}

__global__ void scatter_kernel(const void* __restrict__ ei, int E) {
    int e = blockIdx.x * blockDim.x + threadIdx.x;
    if (e < E) {
        int is64 = g_is64;
        int d = edge_at(ei, E + e, is64);
        int p = g_off[d] + atomicAdd(&g_cur[d], 1);
        g_csr[p] = edge_at(ei, e, is64);
    }
}

// ---------------- SIMT GEMM (decoder) ----------------------------------------
__global__ __launch_bounds__(256)
void gemm_dec(const float* __restrict__ B,
              const float* __restrict__ bias,
              float* __restrict__ C,
              int M, int N, int K)
{
    const float* A = g_X0;
    __shared__ float As[2][16][132];
    __shared__ float Bs[2][16][68];

    const int tid = threadIdx.x;
    const int tx = tid & 15, ty = tid >> 4;
    const int am0 = tid >> 2, am1 = 64 + (tid >> 2), ak4 = tid & 3;
    const int bn0 = tid >> 2, bk4 = tid & 3;
    const int bm = blockIdx.x * 128;

    const float* brow = B + (size_t)bn0 * K;

    float4 pa0, pa1, pb;
    const int nt = K >> 4;

    {
        int gm0 = bm + am0, gm1 = bm + am1;
        pa0 = (gm0 < M) ? *(const float4*)(A + (size_t)gm0 * K + ak4 * 4) : make_float4(0, 0, 0, 0);
        pa1 = (gm1 < M) ? *(const float4*)(A + (size_t)gm1 * K + ak4 * 4) : make_float4(0, 0, 0, 0);
        pb  = (bn0 < N) ? *(const float4*)(brow + bk4 * 4) : make_float4(0, 0, 0, 0);
        As[0][ak4 * 4 + 0][am0] = pa0.x; As[0][ak4 * 4 + 1][am0] = pa0.y;
        As[0][ak4 * 4 + 2][am0] = pa0.z; As[0][ak4 * 4 + 3][am0] = pa0.w;
        As[0][ak4 * 4 + 0][am1] = pa1.x; As[0][ak4 * 4 + 1][am1] = pa1.y;
        As[0][ak4 * 4 + 2][am1] = pa1.z; As[0][ak4 * 4 + 3][am1] = pa1.w;
        Bs[0][bk4 * 4 + 0][bn0] = pb.x;  Bs[0][bk4 * 4 + 1][bn0] = pb.y;
        Bs[0][bk4 * 4 + 2][bn0] = pb.z;  Bs[0][bk4 * 4 + 3][bn0] = pb.w;
    }
    __syncthreads();

    unsigned long long acc[4][4];
    const unsigned long long zz = pk2(0.f, 0.f);
    #pragma unroll
    for (int i = 0; i < 4; i++)
        #pragma unroll
        for (int j = 0; j < 4; j++) acc[i][j] = zz;

    for (int t = 0; t < nt; t++) {
        int cur = t & 1;
        if (t + 1 < nt) {
            int kt = (t + 1) << 4;
            int gm0 = bm + am0, gm1 = bm + am1;
            pa0 = (gm0 < M) ? *(const float4*)(A + (size_t)gm0 * K + kt + ak4 * 4) : make_float4(0, 0, 0, 0);
            pa1 = (gm1 < M) ? *(const float4*)(A + (size_t)gm1 * K + kt + ak4 * 4) : make_float4(0, 0, 0, 0);
            pb  = (bn0 < N) ? *(const float4*)(brow + kt + bk4 * 4) : make_float4(0, 0, 0, 0);
        }
        #pragma unroll
        for (int k = 0; k < 16; k++) {
            ulonglong2 ap0 = *(const ulonglong2*)&As[cur][k][ty * 8];
            ulonglong2 ap1 = *(const ulonglong2*)&As[cur][k][ty * 8 + 4];
            float4 bv = *(const float4*)&Bs[cur][k][tx * 4];
            unsigned long long ad[4] = {ap0.x, ap0.y, ap1.x, ap1.y};
            unsigned long long bd[4] = {pk2(bv.x, bv.x), pk2(bv.y, bv.y),
                                        pk2(bv.z, bv.z), pk2(bv.w, bv.w)};
            #pragma unroll
            for (int i = 0; i < 4; i++) {
                fma2(acc[i][0], ad[i], bd[0]);
                fma2(acc[i][1], ad[i], bd[1]);
                fma2(acc[i][2], ad[i], bd[2]);
                fma2(acc[i][3], ad[i], bd[3]);
            }
        }
        if (t + 1 < nt) {
            int nxt = cur ^ 1;
            As[nxt][ak4 * 4 + 0][am0] = pa0.x; As[nxt][ak4 * 4 + 1][am0] = pa0.y;
            As[nxt][ak4 * 4 + 2][am0] = pa0.z; As[nxt][ak4 * 4 + 3][am0] = pa0.w;
            As[nxt][ak4 * 4 + 0][am1] = pa1.x; As[nxt][ak4 * 4 + 1][am1] = pa1.y;
            As[nxt][ak4 * 4 + 2][am1] = pa1.z; As[nxt][ak4 * 4 + 3][am1] = pa1.w;
            Bs[nxt][bk4 * 4 + 0][bn0] = pb.x;  Bs[nxt][bk4 * 4 + 1][bn0] = pb.y;
            Bs[nxt][bk4 * 4 + 2][bn0] = pb.z;  Bs[nxt][bk4 * 4 + 3][bn0] = pb.w;
            __syncthreads();
        }
    }

    #pragma unroll
    for (int i2 = 0; i2 < 4; i2++) {
        #pragma unroll
        for (int p = 0; p < 2; p++) {
            int gm = bm + ty * 8 + i2 * 2 + p;
            if (gm >= M) continue;
            #pragma unroll
            for (int j = 0; j < 4; j++) {
                float lo, hi;
                upk2(lo, hi, acc[i2][j]);
                float v = p ? hi : lo;
                int gn = tx * 4 + j;
                if (gn >= N) continue;
                v += bias[gn];
                C[(size_t)gm * N + gn] = v;
            }
        }
    }
}

// ---------------- HMMA GEMM (bf16-split-3) -----------------------------------
// EPI 0: layer  — A=g_Xhi/g_Xlo (K=128), B=g_Whi/g_Wlo, out g_U (+res_b cols)
// EPI 1: encoder— A=g_XIhi/g_XIlo (K=256), B=g_Ehi/g_Elo, out relu -> split X
template<int EPI>
__global__ __launch_bounds__(256)
void hmma_gemm(const float* __restrict__ bias)
{
    __shared__ __nv_bfloat16 sAh[128][40];
    __shared__ __nv_bfloat16 sAl[128][40];
    __shared__ __nv_bfloat16 sBh[64][40];
    __shared__ __nv_bfloat16 sBl[64][40];

    const int tid = threadIdx.x;
    const int lane = tid & 31, wid = tid >> 5;
    const int wm = wid >> 1, wn = wid & 1;
    const int bm = blockIdx.x * 128;
    const int tn = blockIdx.y;

    const int K   = (EPI == 1) ? 256 : 128;
    const __nv_bfloat16* Ahi = (EPI == 1) ? g_XIhi : g_Xhi;
    const __nv_bfloat16* Alo = (EPI == 1) ? g_XIlo : g_Xlo;
    const __nv_bfloat16* Bhi = (EPI == 1) ? g_Ehi : g_Whi;
    const __nv_bfloat16* Blo = (EPI == 1) ? g_Elo : g_Wlo;
    const size_t bnrow = (size_t)tn * 64;

    float acc[2][4][4];
    #pragma unroll
    for (int i = 0; i < 2; i++)
        #pragma unroll
        for (int j = 0; j < 4; j++)
            #pragma unroll
            for (int q = 0; q < 4; q++) acc[i][j][q] = 0.f;

    const uint32_t aHiB = smem_u32(&sAh[0][0]);
    const uint32_t aLoB = smem_u32(&sAl[0][0]);
    const uint32_t bHiB = smem_u32(&sBh[0][0]);
    const uint32_t bLoB = smem_u32(&sBl[0][0]);

    const int aRow = wm * 32 + (lane & 15);
    const int aColOff = (lane >> 4) * 8;
    const int bRow = wn * 32 + (lane & 7) + ((lane >> 4) & 1) * 8;
    const int bColOff = ((lane >> 3) & 1) * 8;

    for (int kc = 0; kc < K; kc += 32) {
        #pragma unroll
        for (int i = 0; i < 2; i++) {
            int idx = tid + i * 256;
            int r = idx >> 2, q = idx & 3;
            size_t src = (size_t)(bm + r) * K + kc + q * 8;
            *(uint4*)&sAh[r][q * 8] = *(const uint4*)(Ahi + src);
            *(uint4*)&sAl[r][q * 8] = *(const uint4*)(Alo + src);
        }
        {
            int r = tid >> 2, q = tid & 3;
            size_t src = (bnrow + r) * K + kc + q * 8;
            *(uint4*)&sBh[r][q * 8] = *(const uint4*)(Bhi + src);
            *(uint4*)&sBl[r][q * 8] = *(const uint4*)(Blo + src);
        }
        __syncthreads();

        #pragma unroll
        for (int ks = 0; ks < 2; ks++) {
            int kk = ks * 16;
            uint32_t ah[2][4], al[2][4];
            #pragma unroll
            for (int mi = 0; mi < 2; mi++) {
                uint32_t off = (uint32_t)(((aRow + mi * 16) * 40 + kk + aColOff) * 2);
                LDSM_X4(ah[mi], aHiB + off);
                LDSM_X4(al[mi], aLoB + off);
            }
            uint32_t bh0[4], bl0[4], bh1[4], bl1[4];
            {
                uint32_t off0 = (uint32_t)((bRow * 40 + kk + bColOff) * 2);
                uint32_t off1 = (uint32_t)(((bRow + 16) * 40 + kk + bColOff) * 2);
                LDSM_X4(bh0, bHiB + off0);
                LDSM_X4(bl0, bLoB + off0);
                LDSM_X4(bh1, bHiB + off1);
                LDSM_X4(bl1, bLoB + off1);
            }
            #pragma unroll
            for (int mi = 0; mi < 2; mi++) {
                MMA_BF16(acc[mi][0], ah[mi], bh0[0], bh0[1]);
                MMA_BF16(acc[mi][0], ah[mi], bl0[0], bl0[1]);
                MMA_BF16(acc[mi][0], al[mi], bh0[0], bh0[1]);
                MMA_BF16(acc[mi][1], ah[mi], bh0[2], bh0[3]);
                MMA_BF16(acc[mi][1], ah[mi], bl0[2], bl0[3]);
                MMA_BF16(acc[mi][1], al[mi], bh0[2], bh0[3]);
                MMA_BF16(acc[mi][2], ah[mi], bh1[0], bh1[1]);
                MMA_BF16(acc[mi][2], ah[mi], bl1[0], bl1[1]);
                MMA_BF16(acc[mi][2], al[mi], bh1[0], bh1[1]);
                MMA_BF16(acc[mi][3], ah[mi], bh1[2], bh1[3]);
                MMA_BF16(acc[mi][3], ah[mi], bl1[2], bl1[3]);
                MMA_BF16(acc[mi][3], al[mi], bh1[2], bh1[3]);
            }
        }
        __syncthreads();
    }

    const int g = lane >> 2, tig = lane & 3;
    #pragma unroll
    for (int mi = 0; mi < 2; mi++) {
        #pragma unroll
        for (int ni = 0; ni < 4; ni++) {
            int gn = tn * 64 + wn * 32 + ni * 8 + tig * 2;
            int gm0 = bm + wm * 32 + mi * 16 + g;
            if (EPI == 0) {
                if (gn >= UC) continue;
                const bool isres = (tn >= 8 && tn < 16);
                float bx = 0.f, by = 0.f;
                if (isres) { bx = bias[gn - 512]; by = bias[gn - 511]; }
                if (gm0 < NNODES) {
                    float2 o = make_float2(acc[mi][ni][0] + bx, acc[mi][ni][1] + by);
                    *(float2*)(g_U + (size_t)gm0 * UC + gn) = o;
                }
                int gm1 = gm0 + 8;
                if (gm1 < NNODES) {
                    float2 o = make_float2(acc[mi][ni][2] + bx, acc[mi][ni][3] + by);
                    *(float2*)(g_U + (size_t)gm1 * UC + gn) = o;
                }
            } else {
                float bx = bias[gn], by = bias[gn + 1];
                if (gm0 < NNODES) {
                    float vx = fmaxf(acc[mi][ni][0] + bx, 0.f);
                    float vy = fmaxf(acc[mi][ni][1] + by, 0.f);
                    split_write2(g_Xhi, g_Xlo, (size_t)gm0 * 128 + gn, vx, vy);
                }
                int gm1 = gm0 + 8;
                if (gm1 < NNODES) {
                    float vx = fmaxf(acc[mi][ni][2] + bx, 0.f);
                    float vy = fmaxf(acc[mi][ni][3] + by, 0.f);
                    split_write2(g_Xhi, g_Xlo, (size_t)gm1 * 128 + gn, vx, vy);
                }
            }
        }
    }
}

// ---------------- GAT aggregation + fused GraphCON epilogue ----------------
// Barrier-free: warp w = head w; per-edge weights computed one-per-lane and
// broadcast with shuffles. Numerically identical edge order per channel.
// MODE 0: layer 0 — writes split X (next HMMA input), re-zeroes deg/cur
// MODE 1: layer 1 — writes fp32 g_X0 (decoder input)
template<int MODE>
__global__ __launch_bounds__(128)
void node_kernel(const float* __restrict__ gat_b)
{
    const int d = blockIdx.x, t = threadIdx.x;
    const int h = t >> 5, lane = t & 31;

    const float* ud = g_U + (size_t)d * UC;
    float4 acc = ((const float4*)ud)[t];         // self contribution (w = 1)
    const float adv = ud[1028 + h];              // warp-uniform
    const float ls  = lrelu(ud[1024 + h] + adv); // self logit (stabilizer)

    if (MODE == 0 && t == 0) { g_deg[d] = 0; g_cur[d] = 0; }

    const int e0 = g_off[d], e1 = g_off[d + 1];
    float ssum = 1.f;

    for (int base = e0; base < e1; base += 32) {
        int cnt = min(32, e1 - base);
        int   sreg = 0;
        float wreg = 0.f;
        if (lane < cnt) {
            sreg = g_csr[base + lane];
            float as = g_U[(size_t)sreg * UC + 1024 + h];
            wreg = __expf(lrelu(as + adv) - ls);
        }
        int j = 0;
        for (; j + 4 <= cnt; j += 4) {
            int   s0 = __shfl_sync(0xffffffffu, sreg, j);
            int   s1 = __shfl_sync(0xffffffffu, sreg, j + 1);
            int   s2 = __shfl_sync(0xffffffffu, sreg, j + 2);
            int   s3 = __shfl_sync(0xffffffffu, sreg, j + 3);
            float w0 = __shfl_sync(0xffffffffu, wreg, j);
            float w1 = __shfl_sync(0xffffffffu, wreg, j + 1);
            float w2 = __shfl_sync(0xffffffffu, wreg, j + 2);
            float w3 = __shfl_sync(0xffffffffu, wreg, j + 3);
            float4 v0 = ((const float4*)(g_U + (size_t)s0 * UC))[t];
            float4 v1 = ((const float4*)(g_U + (size_t)s1 * UC))[t];
            float4 v2 = ((const float4*)(g_U + (size_t)s2 * UC))[t];
            float4 v3 = ((const float4*)(g_U + (size_t)s3 * UC))[t];
            acc.x = fmaf(w0, v0.x, acc.x); acc.y = fmaf(w0, v0.y, acc.y);
            acc.z = fmaf(w0, v0.z, acc.z); acc.w = fmaf(w0, v0.w, acc.w);
            acc.x = fmaf(w1, v1.x, acc.x); acc.y = fmaf(w1, v1.y, acc.y);
            acc.z = fmaf(w1, v1.z, acc.z); acc.w = fmaf(w1, v1.w, acc.w);
            acc.x = fmaf(w2, v2.x, acc.x); acc.y = fmaf(w2, v2.y, acc.y);
            acc.z = fmaf(w2, v2.z, acc.z); acc.w = fmaf(w2, v2.w, acc.w);
            acc.x = fmaf(w3, v3.x, acc.x); acc.y = fmaf(w3, v3.y, acc.y);
            acc.z = fmaf(w3, v3.z, acc.z); acc.w = fmaf(w3, v3.w, acc.w);
            ssum += (w0 + w1) + (w2 + w3);
        }
        for (; j < cnt; j++) {
            int   s0 = __shfl_sync(0xffffffffu, sreg, j);
            float w0 = __shfl_sync(0xffffffffu, wreg, j);
            float4 v0 = ((const float4*)(g_U + (size_t)s0 * UC))[t];
            acc.x = fmaf(w0, v0.x, acc.x); acc.y = fmaf(w0, v0.y, acc.y);
            acc.z = fmaf(w0, v0.z, acc.z); acc.w = fmaf(w0, v0.w, acc.w);
            ssum += w0;
        }
    }

    float rcp = 1.f / ssum;
    float4 gb = ((const float4*)gat_b)[t];
    float4 rs = ((const float4*)(ud + 512))[t];
    float z = 0.25f * (eluf(fmaf(acc.x, rcp, gb.x + rs.x)) +
                       eluf(fmaf(acc.y, rcp, gb.y + rs.y)) +
                       eluf(fmaf(acc.z, rcp, gb.z + rs.z)) +
                       eluf(fmaf(acc.w, rcp, gb.w + rs.w)));

    size_t o = (size_t)d * NHID + t;
    if (MODE == 0) {
        split_write(g_Xhi, g_Xlo, o, z);
    } else {
        g_X0[o] = z;
    }
}

// ---------------- host ------------------------------------------------------
extern "C" void kernel_launch(void* const* d_in, const int* in_sizes, int n_in,
                              void* d_out, int out_size)
{
    const float* x       = (const float*)d_in[0];
    const void*  ei      = d_in[1];
    const float* enc_w   = (const float*)d_in[2];
    const float* enc_b   = (const float*)d_in[3];
    const float* res_w   = (const float*)d_in[4];
    const float* res_b   = (const float*)d_in[5];
    const float* gat_w   = (const float*)d_in[6];
    const float* att_src = (const float*)d_in[7];
    const float* att_dst = (const float*)d_in[8];
    const float* gat_b   = (const float*)d_in[9];
    const float* dec_w   = (const float*)d_in[10];
    const float* dec_b   = (const float*)d_in[11];
    int E = in_sizes[1] / 2;

    cudaStream_t s2;
    cudaStreamCreateWithFlags(&s2, cudaStreamNonBlocking);
    cudaEvent_t evA, evW, evB;
    cudaEventCreateWithFlags(&evA, cudaEventDisableTiming);
    cudaEventCreateWithFlags(&evW, cudaEventDisableTiming);
    cudaEventCreateWithFlags(&evB, cudaEventDisableTiming);

    // folds + dtype sniff (small, fast)
    init_kernel<<<9, 128>>>(ei, gat_w, att_src, att_dst);

    // fork EARLY: conv_w (needs folds) + CSR build on side stream
    cudaEventRecord(evA, 0);
    cudaStreamWaitEvent(s2, evA, 0);
    conv_w_kernel<<<NBPAD, 128, 0, s2>>>(gat_w, res_w);
    cudaEventRecord(evW, s2);
    count_kernel<<<(E + 255) / 256, 256, 0, s2>>>(ei, E);
    scan_kernel<<<1, 1024, 0, s2>>>(NNODES);
    scatter_kernel<<<(E + 255) / 256, 256, 0, s2>>>(ei, E);
    cudaEventRecord(evB, s2);

    // x + enc_w split on main stream (overlap with side-stream work)
    conv_x_kernel<<<NPAD + 128, 256>>>(x, enc_w);

    // encoder (HMMA): split(relu(x @ enc_w^T + enc_b))
    hmma_gemm<1><<<dim3(79, 2), 256>>>(enc_b);

    // layer 0 (GEMM needs conv_w; node needs CSR)
    cudaStreamWaitEvent(0, evW, 0);
    hmma_gemm<0><<<dim3(79, 17), 256>>>(res_b);
    cudaStreamWaitEvent(0, evB, 0);
    node_kernel<0><<<NNODES, 128>>>(gat_b);

    // layer 1
    hmma_gemm<0><<<dim3(79, 17), 256>>>(res_b);
    node_kernel<1><<<NNODES, 128>>>(gat_b);

    // decoder: out = z @ dec_w^T + dec_b
    gemm_dec<<<79, 256>>>(dec_w, dec_b, (float*)d_out, NNODES, 40, 128);
}